// round 13
// baseline (speedup 1.0000x reference)
#include <cuda_runtime.h>
#include <cuda_bf16.h>
#include <math.h>
#include <stdint.h>

#define BATCH   2
#define IMH     256
#define IMW     256
#define C       192
#define HEADS   6
#define HD      32
#define HIDDEN  768
#define HW      (IMH*IMW)
#define M_TOK   (BATCH*HW)          // 131072
#define SCALE_Q 0.17677669529663687f

typedef __nv_bfloat16  bf16;
typedef __nv_bfloat162 bf162;

// ---------------- scratch buffers (device globals; no allocation) -----------
__device__ bf16  g_xn  [M_TOK * C];
__device__ bf16  g_q   [M_TOK * C];
__device__ bf16  g_kv  [M_TOK * (C/2)];
__device__ bf16  g_aw  [M_TOK * C];
__device__ float g_xmid[M_TOK * C];
__device__ bf16  g_h1  [(size_t)M_TOK * HIDDEN];
__device__ bf16  g_h2  [(size_t)M_TOK * HIDDEN];
__device__ bf16  g_wp  [387072];     // packed [N][K] bf16 weights
#define WP_Q    0
#define WP_KV   36864
#define WP_PROJ 55296
#define WP_F1   92160
#define WP_F2   239616

__device__ __forceinline__ uint32_t bf2(float lo, float hi) {
    bf162 h = __floats2bfloat162_rn(lo, hi);
    return *(uint32_t*)&h;
}

// ---------------- weight pre-pack (all 5 matrices, one launch) --------------
__global__ void pack_all(const float* __restrict__ wq,
                         const float* __restrict__ wkv,
                         const float* __restrict__ wproj,
                         const float* __restrict__ w1f,
                         const float* __restrict__ w2f,
                         bf16* __restrict__ out) {
    int idx = blockIdx.x * 256 + threadIdx.x;
    if (idx >= 387072) return;
    const float* W; int K, N, off;
    if      (idx < WP_KV)   { W = wq;    K = 192; N = 192; off = WP_Q;    }
    else if (idx < WP_PROJ) { W = wkv;   K = 192; N = 96;  off = WP_KV;   }
    else if (idx < WP_F1)   { W = wproj; K = 192; N = 192; off = WP_PROJ; }
    else if (idx < WP_F2)   { W = w1f;   K = 192; N = 768; off = WP_F1;   }
    else                    { W = w2f;   K = 768; N = 192; off = WP_F2;   }
    int li = idx - off;
    int n = li / K, k = li - n * K;
    out[idx] = __float2bfloat16(W[(size_t)k * N + n]);
}

// ---------------- LayerNorm: one warp per token, contiguous 6/thread --------
__global__ void ln_kernel(const float* __restrict__ x,
                          const float* __restrict__ g,
                          const float* __restrict__ b,
                          bf16* __restrict__ out) {
    int token = blockIdx.x * blockDim.y + threadIdx.y;
    int lane  = threadIdx.x;
    const float* row = x + (size_t)token * C + lane * 6;
    float v[6];
#pragma unroll
    for (int i = 0; i < 3; i++)
        *(float2*)&v[2*i] = *(const float2*)(row + 2*i);
    float s = 0.f;
#pragma unroll
    for (int i = 0; i < 6; i++) s += v[i];
#pragma unroll
    for (int o = 16; o > 0; o >>= 1) s += __shfl_xor_sync(0xffffffffu, s, o);
    float mean = s * (1.0f / C);
    float s2 = 0.f;
#pragma unroll
    for (int i = 0; i < 6; i++) { float d = v[i] - mean; s2 += d * d; }
#pragma unroll
    for (int o = 16; o > 0; o >>= 1) s2 += __shfl_xor_sync(0xffffffffu, s2, o);
    float rstd = rsqrtf(s2 * (1.0f / C) + 1e-5f);
    float gv[6], bv[6];
#pragma unroll
    for (int i = 0; i < 3; i++) {
        *(float2*)&gv[2*i] = *(const float2*)(g + lane*6 + 2*i);
        *(float2*)&bv[2*i] = *(const float2*)(b + lane*6 + 2*i);
    }
    uint32_t* orow = (uint32_t*)(out + (size_t)token * C + lane * 6);
#pragma unroll
    for (int i = 0; i < 3; i++) {
        float a0 = (v[2*i]   - mean) * rstd * gv[2*i]   + bv[2*i];
        float a1 = (v[2*i+1] - mean) * rstd * gv[2*i+1] + bv[2*i+1];
        orow[i] = bf2(a0, a1);
    }
}

// ---------------- persistent bf16 tensor-core GEMM --------------------------
// OUT[M,N] = epi( A[M,K] @ Wp^T + bias ), Wp packed [N][K] bf16.
// BM=128, BN=96, BK=32, 256 threads = 8 warps 4(m)x2(n), warp tile 32x48.
// Each CTA processes CH_M m-tiles; cp.async pipeline runs CONTINUOUSLY
// across m-tile boundaries (one fill per CTA, not per tile).
// Rows padded 64B->80B (5x16B): conflict-free ldmatrix without swizzle.

#define STAGES      4
#define CH_M        8
#define A_STAGE_B   (128*80)                 // 10240
#define B_STAGE_B   (96*80)                  // 7680
#define STAGE_B     (A_STAGE_B + B_STAGE_B)  // 17920
#define GSMEM_TOTAL (STAGES * STAGE_B)       // 71680

__device__ __forceinline__ void mma_bf16(float* d, const uint32_t* a,
                                         uint32_t b0, uint32_t b1) {
    asm volatile(
        "mma.sync.aligned.m16n8k16.row.col.f32.bf16.bf16.f32 "
        "{%0,%1,%2,%3},{%4,%5,%6,%7},{%8,%9},{%0,%1,%2,%3};"
        : "+f"(d[0]), "+f"(d[1]), "+f"(d[2]), "+f"(d[3])
        : "r"(a[0]), "r"(a[1]), "r"(a[2]), "r"(a[3]), "r"(b0), "r"(b1));
}
__device__ __forceinline__ void ldsm4(uint32_t& r0, uint32_t& r1,
                                      uint32_t& r2, uint32_t& r3,
                                      uint32_t addr) {
    asm volatile(
        "ldmatrix.sync.aligned.m8n8.x4.shared.b16 {%0,%1,%2,%3}, [%4];"
        : "=r"(r0), "=r"(r1), "=r"(r2), "=r"(r3) : "r"(addr));
}
__device__ __forceinline__ void cp16(uint32_t dst, const void* src) {
    asm volatile("cp.async.cg.shared.global [%0], [%1], 16;"
                 :: "r"(dst), "l"(src));
}
#define CP_COMMIT()  asm volatile("cp.async.commit_group;")
#define CP_WAIT2()   asm volatile("cp.async.wait_group 2;")

__device__ __forceinline__ uint32_t smem_u32(const void* p) {
    uint32_t a;
    asm("{ .reg .u64 t; cvta.to.shared.u64 t, %1; cvt.u32.u64 %0, t; }"
        : "=r"(a) : "l"(p));
    return a;
}

__device__ __forceinline__ void
issue_stage(uint32_t sbase, int stage, const bf16* __restrict__ A,
            const bf16* __restrict__ Wp, int K, int m0, int n0,
            int kt, int tid) {
    uint32_t ab = sbase + stage * STAGE_B;
    uint32_t bb = ab + A_STAGE_B;
#pragma unroll
    for (int r = 0; r < 2; r++) {
        int i = tid + r * 256;
        cp16(ab + (((i >> 2) * 5 + (i & 3)) << 4),
             A + (size_t)(m0 + (i >> 2)) * K + kt * 32 + (i & 3) * 8);
    }
    cp16(bb + (((tid >> 2) * 5 + (tid & 3)) << 4),
         Wp + (size_t)(n0 + (tid >> 2)) * K + kt * 32 + (tid & 3) * 8);
    if (tid < 128) {
        int i = tid + 256;
        cp16(bb + (((i >> 2) * 5 + (i & 3)) << 4),
             Wp + (size_t)(n0 + (i >> 2)) * K + kt * 32 + (i & 3) * 8);
    }
}

template<int EPI, bool OUT_BF16>
__device__ __forceinline__ void
gemm_body(char* sm, const bf16* __restrict__ A, const bf16* __restrict__ Wp,
          const float* __restrict__ bias, const float* __restrict__ res,
          void* __restrict__ outv, int N, int K, int n0, int mtile0) {
    const int tid  = threadIdx.x;
    const int wid  = tid >> 5, lane = tid & 31;
    const int wm   = wid >> 1, wn = wid & 1;
    const int gid  = lane >> 2, tig = lane & 3;

    uint32_t sbase = smem_u32(sm);

    uint32_t a_off[2], b_off[3];
#pragma unroll
    for (int mt = 0; mt < 2; mt++)
        a_off[mt] = ((wm*32 + mt*16 + (lane & 15)) * 5 + (lane >> 4)) * 16;
#pragma unroll
    for (int p = 0; p < 3; p++)
        b_off[p] = A_STAGE_B +
            ((wn*48 + p*16 + ((lane >> 4) & 1)*8 + (lane & 7)) * 5 +
             ((lane >> 3) & 1)) * 16;

    const int nk = K / 32;

    // issue cursor (decoupled from compute)
    int imt = mtile0, ikt = 0;
    const int imt_end = mtile0 + CH_M;

    // prologue: STAGES-1 stages in flight
#pragma unroll
    for (int p = 0; p < STAGES - 1; p++) {
        issue_stage(sbase, p, A, Wp, K, imt * 128, n0, ikt, tid);
        if (++ikt == nk) { ikt = 0; imt++; }
        CP_COMMIT();
    }

    int stage = 0;
    for (int mti = 0; mti < CH_M; mti++) {
        int m0 = (mtile0 + mti) * 128;

        float acc[2][6][4];
#pragma unroll
        for (int mt = 0; mt < 2; mt++)
#pragma unroll
            for (int nt = 0; nt < 6; nt++)
#pragma unroll
                for (int r = 0; r < 4; r++) acc[mt][nt][r] = 0.f;

        for (int kt = 0; kt < nk; kt++) {
            CP_WAIT2();
            __syncthreads();

            uint32_t sb = sbase + stage * STAGE_B;
#pragma unroll
            for (int s = 0; s < 2; s++) {
                uint32_t af[2][4];
#pragma unroll
                for (int mt = 0; mt < 2; mt++)
                    ldsm4(af[mt][0], af[mt][1], af[mt][2], af[mt][3],
                          sb + a_off[mt] + s*32);
                uint32_t bfr[3][4];
#pragma unroll
                for (int p = 0; p < 3; p++)
                    ldsm4(bfr[p][0], bfr[p][1], bfr[p][2], bfr[p][3],
                          sb + b_off[p] + s*32);
#pragma unroll
                for (int nt = 0; nt < 6; nt++) {
                    uint32_t b0 = bfr[nt >> 1][(nt & 1)*2];
                    uint32_t b1 = bfr[nt >> 1][(nt & 1)*2 + 1];
#pragma unroll
                    for (int mt = 0; mt < 2; mt++)
                        mma_bf16(acc[mt][nt], af[mt], b0, b1);
                }
            }

            if (imt < imt_end) {
                int ns = stage + STAGES - 1;
                if (ns >= STAGES) ns -= STAGES;
                issue_stage(sbase, ns, A, Wp, K, imt * 128, n0, ikt, tid);
                if (++ikt == nk) { ikt = 0; imt++; }
            }
            CP_COMMIT();
            if (++stage == STAGES) stage = 0;
        }

        // epilogue for this m-tile (registers + gmem only; no smem touch)
#pragma unroll
        for (int nt = 0; nt < 6; nt++) {
            int cb = n0 + wn*48 + nt*8 + 2*tig;
            float b0 = bias[cb], b1 = bias[cb + 1];
#pragma unroll
            for (int mt = 0; mt < 2; mt++) {
                int r0 = m0 + wm*32 + mt*16 + gid;
#pragma unroll
                for (int hh = 0; hh < 2; hh++) {
                    int r = r0 + hh*8;
                    float v0 = acc[mt][nt][hh*2 + 0] + b0;
                    float v1 = acc[mt][nt][hh*2 + 1] + b1;
                    if (EPI == 1) {
                        v0 = v0 * normcdff(v0); v1 = v1 * normcdff(v1);
                    }
                    if (EPI == 2) {
                        const float* rr = res + (size_t)r * N + cb;
                        v0 += rr[0]; v1 += rr[1];
                    }
                    if (OUT_BF16)
                        *(uint32_t*)((bf16*)outv + (size_t)r * N + cb) =
                            bf2(v0, v1);
                    else
                        *(float2*)((float*)outv + (size_t)r * N + cb) =
                            make_float2(v0, v1);
                }
            }
        }
    }
}

template<int EPI, bool OUT_BF16>
__global__ void __launch_bounds__(256, 2)
gemm_k(const bf16* __restrict__ A, const bf16* __restrict__ Wp,
       const float* __restrict__ bias, const float* __restrict__ res,
       void* __restrict__ out, int N, int K) {
    extern __shared__ char sm[];
    gemm_body<EPI, OUT_BF16>(sm, A, Wp, bias, res, out, N, K,
                             blockIdx.x * 96, blockIdx.y * CH_M);
}

__global__ void __launch_bounds__(256, 2)
gemm_qkv(const bf16* __restrict__ A,
         const bf16* __restrict__ Wq,  const float* __restrict__ bq,
         bf16* __restrict__ qout,
         const bf16* __restrict__ Wkv, const float* __restrict__ bkv,
         bf16* __restrict__ kvout) {
    extern __shared__ char sm[];
    if (blockIdx.x < 2)
        gemm_body<0, true>(sm, A, Wq, bq, nullptr, qout, 192, 192,
                           blockIdx.x * 96, blockIdx.y * CH_M);
    else
        gemm_body<0, true>(sm, A, Wkv, bkv, nullptr, kvout, 96, 192,
                           0, blockIdx.y * CH_M);
}

// ---------------- fused window attention (bf16 I/O) -------------------------
__global__ void __launch_bounds__(384)
attn_kernel(const bf16* __restrict__ q, const bf16* __restrict__ kv,
            const float* __restrict__ table, bf16* __restrict__ aw) {
    __shared__ float ks[16*192];
    __shared__ float vs[16*192];
    __shared__ float tb[49*HEADS];

    int w  = blockIdx.x;
    int bb = w >> 10;
    int wi = w & 1023;
    int wy = wi >> 5, wx = wi & 31;
    size_t base = (size_t)bb * HW + (size_t)(wy*8) * IMW + wx*8;
    int tid = threadIdx.x;

    for (int e = tid; e < 49*HEADS; e += 384) tb[e] = table[e];

    for (int e = tid; e < 64*48; e += 384) {
        int s  = e / 48, cc = e - s*48;
        int r  = s >> 3, c = s & 7;
        int p  = (r >> 1) * 4 + (c >> 1);
        int f  = (r & 1) * 96 + (c & 1) * 48 + cc;
        const bf16* src = kv + (base + (size_t)r * IMW + c) * (C/2);
        ks[p*192 + f] = __bfloat162float(src[cc]);
        vs[p*192 + f] = __bfloat162float(src[48 + cc]);
    }
    __syncthreads();

    int h  = tid / 64;
    int qt = tid & 63;
    int r  = qt >> 3, c = qt & 7;
    int ph = r >> 1, pw = c >> 1;

    size_t tok = base + (size_t)r * IMW + c;
    const uint4* q4 = (const uint4*)(q + tok * C + h*HD);
    float qr[HD];
#pragma unroll
    for (int i = 0; i < 4; i++) {
        uint4 t = q4[i];
        uint32_t u[4] = {t.x, t.y, t.z, t.w};
#pragma unroll
        for (int j = 0; j < 4; j++) {
            float2 f2 = __bfloat1622float2(*(bf162*)&u[j]);
            qr[i*8 + 2*j]     = f2.x * SCALE_Q;
            qr[i*8 + 2*j + 1] = f2.y * SCALE_Q;
        }
    }

    float s[16], m = -1e30f;
#pragma unroll
    for (int kt = 0; kt < 16; kt++) {
        int kh = kt >> 2, kw = kt & 3;
        float acc = tb[((ph - kh + 3) * 7 + (pw - kw + 3)) * HEADS + h];
        const float* kr = &ks[kt*192 + h*HD];
#pragma unroll
        for (int d = 0; d < HD; d++) acc += qr[d] * kr[d];
        s[kt] = acc;
        m = fmaxf(m, acc);
    }
    float sum = 0.f;
#pragma unroll
    for (int kt = 0; kt < 16; kt++) { s[kt] = __expf(s[kt] - m); sum += s[kt]; }
    float inv = 1.0f / sum;

    float ov[HD];
#pragma unroll
    for (int d = 0; d < HD; d++) {
        float o = 0.f;
#pragma unroll
        for (int kt = 0; kt < 16; kt++) o += s[kt] * vs[kt*192 + h*HD + d];
        ov[d] = o * inv;
    }
    uint4* ow = (uint4*)(aw + tok * C + h*HD);
#pragma unroll
    for (int i = 0; i < 4; i++) {
        uint4 t;
        t.x = bf2(ov[i*8+0], ov[i*8+1]);
        t.y = bf2(ov[i*8+2], ov[i*8+3]);
        t.z = bf2(ov[i*8+4], ov[i*8+5]);
        t.w = bf2(ov[i*8+6], ov[i*8+7]);
        ow[i] = t;
    }
}

// ---------------- depthwise 5x5 conv + gelu + add (bf16 I/O) ----------------
__global__ void __launch_bounds__(256)
dwconv_kernel(const bf16* __restrict__ h1, const float* __restrict__ dwk,
              const float* __restrict__ dwb, bf16* __restrict__ out) {
    constexpr int TS = 16, CCH = 32, TT = TS + 4;
    extern __shared__ float smem[];
    float* tile = smem;
    float* wk   = tile + TT*TT*CCH;
    float* bk   = wk + CCH*25;

    int bz = blockIdx.z;
    int bb = bz / (HIDDEN / CCH);
    int c0 = (bz % (HIDDEN / CCH)) * CCH;
    int x0 = blockIdx.x * TS, y0 = blockIdx.y * TS;
    int tid = threadIdx.x;

    for (int e = tid; e < CCH*25; e += 256) {
        int cc = e / 25, t = e - cc*25;
        wk[cc*25 + t] = dwk[(c0 + cc) * 25 + t];
    }
    if (tid < CCH) bk[tid] = dwb[c0 + tid];

    for (int e = tid; e < TT*TT*(CCH/8); e += 256) {
        int pos = e / (CCH/8);
        int qv  = e - pos*(CCH/8);
        int py = pos / TT, px = pos - py*TT;
        int gy = y0 + py - 2, gx = x0 + px - 2;
        float f[8] = {0,0,0,0,0,0,0,0};
        if (gy >= 0 && gy < IMH && gx >= 0 && gx < IMW) {
            uint4 t = *(const uint4*)(h1 +
                ((size_t)bb*HW + (size_t)gy*IMW + gx)*HIDDEN + c0 + qv*8);
            uint32_t u[4] = {t.x, t.y, t.z, t.w};
#pragma unroll
            for (int j = 0; j < 4; j++) {
                float2 f2 = __bfloat1622float2(*(bf162*)&u[j]);
                f[2*j] = f2.x; f[2*j+1] = f2.y;
            }
        }
        float* dst = &tile[(py*TT + px)*CCH + qv*8];
#pragma unroll
        for (int j = 0; j < 8; j++) dst[j] = f[j];
    }
    __syncthreads();

    int cc = tid & (CCH-1);
    int st = tid >> 5;
    const float* wr = &wk[cc*25];
    float bia = bk[cc];

    for (int it = 0; it < 8; it++) {
        int task = it*8 + st;
        int x  = task & 15;
        int ys = task >> 4;
        float acc[4] = {0.f, 0.f, 0.f, 0.f};
#pragma unroll
        for (int rr = 0; rr < 8; rr++) {
            int py = ys*4 + rr;
            float v[5];
#pragma unroll
            for (int dx = 0; dx < 5; dx++)
                v[dx] = tile[(py*TT + x + dx)*CCH + cc];
#pragma unroll
            for (int j = 0; j < 4; j++) {
                int ky = rr - j;
                if (ky >= 0 && ky < 5) {
#pragma unroll
                    for (int dx = 0; dx < 5; dx++)
                        acc[j] += v[dx] * wr[ky*5 + dx];
                }
            }
        }
#pragma unroll
        for (int j = 0; j < 4; j++) {
            int y = ys*4 + j;
            float rj = tile[((y+2)*TT + (x+2))*CCH + cc];
            float gv = acc[j] + bia;
            gv = gv * normcdff(gv);
            size_t o = ((size_t)bb*HW + (size_t)(y0+y)*IMW + (x0+x))*HIDDEN
                     + c0 + cc;
            out[o] = __float2bfloat16(rj + gv);
        }
    }
}

// ---------------- launch ----------------------------------------------------
extern "C" void kernel_launch(void* const* d_in, const int* in_sizes, int n_in,
                              void* d_out, int out_size) {
    const float* x     = (const float*)d_in[0];
    const float* g1    = (const float*)d_in[1];
    const float* be1   = (const float*)d_in[2];
    const float* wq    = (const float*)d_in[3];
    const float* bq    = (const float*)d_in[4];
    const float* wkv   = (const float*)d_in[5];
    const float* bkv   = (const float*)d_in[6];
    const float* table = (const float*)d_in[7];
    const float* wproj = (const float*)d_in[8];
    const float* bproj = (const float*)d_in[9];
    const float* g2    = (const float*)d_in[10];
    const float* be2   = (const float*)d_in[11];
    const float* w1f   = (const float*)d_in[12];
    const float* b1f   = (const float*)d_in[13];
    const float* dwk   = (const float*)d_in[14];
    const float* dwb   = (const float*)d_in[15];
    const float* w2f   = (const float*)d_in[16];
    const float* b2f   = (const float*)d_in[17];
    float* out = (float*)d_out;

    void *pxn, *pq, *pkv, *paw, *pxmid, *ph1, *ph2, *pwp;
    cudaGetSymbolAddress(&pxn,   g_xn);
    cudaGetSymbolAddress(&pq,    g_q);
    cudaGetSymbolAddress(&pkv,   g_kv);
    cudaGetSymbolAddress(&paw,   g_aw);
    cudaGetSymbolAddress(&pxmid, g_xmid);
    cudaGetSymbolAddress(&ph1,   g_h1);
    cudaGetSymbolAddress(&ph2,   g_h2);
    cudaGetSymbolAddress(&pwp,   g_wp);
    bf16*  xn   = (bf16*)pxn;
    bf16*  qb   = (bf16*)pq;
    bf16*  kvb  = (bf16*)pkv;
    bf16*  awb  = (bf16*)paw;
    float* xmid = (float*)pxmid;
    bf16*  h1   = (bf16*)ph1;
    bf16*  h2   = (bf16*)ph2;
    bf16*  wp   = (bf16*)pwp;

    const int CSMEM = (20*20*32 + 32*25 + 32) * 4;
    cudaFuncSetAttribute(dwconv_kernel,
        cudaFuncAttributeMaxDynamicSharedMemorySize, CSMEM);
    cudaFuncSetAttribute(gemm_k<2, false>,
        cudaFuncAttributeMaxDynamicSharedMemorySize, GSMEM_TOTAL);
    cudaFuncSetAttribute(gemm_k<1, true>,
        cudaFuncAttributeMaxDynamicSharedMemorySize, GSMEM_TOTAL);
    cudaFuncSetAttribute(gemm_qkv,
        cudaFuncAttributeMaxDynamicSharedMemorySize, GSMEM_TOTAL);

    dim3 lnb(32, 8);
    const int MCH = M_TOK / 128 / CH_M;   // 128 chunks

    // 0) pack all weights to bf16 [N][K]
    pack_all<<<(387072 + 255)/256, 256>>>(wq, wkv, wproj, w1f, w2f, wp);

    // 1) LN1 -> xn (bf16)
    ln_kernel<<<M_TOK/8, lnb>>>(x, g1, be1, xn);
    // 2+3) fused q & kv projections
    gemm_qkv<<<dim3(3, MCH), 256, GSMEM_TOTAL>>>(xn, wp + WP_Q, bq, qb,
                                                 wp + WP_KV, bkv, kvb);
    // 4) window attention -> aw (bf16)
    attn_kernel<<<2048, 384>>>(qb, kvb, table, awb);
    // 5) xmid = x + aw @ wproj + bproj (fp32 out)
    gemm_k<2, false><<<dim3(2, MCH), 256, GSMEM_TOTAL>>>(
        awb, wp + WP_PROJ, bproj, x, xmid, 192, 192);
    // 6) LN2 -> xn
    ln_kernel<<<M_TOK/8, lnb>>>(xmid, g2, be2, xn);
    // 7) h1 = gelu(xn @ w1f + b1f)
    gemm_k<1, true><<<dim3(8, MCH), 256, GSMEM_TOTAL>>>(
        xn, wp + WP_F1, b1f, nullptr, h1, 768, 192);
    // 8) h2 = h1 + gelu(dwconv(h1) + dwb)
    dwconv_kernel<<<dim3(IMW/16, IMH/16, BATCH*(HIDDEN/32)), 256, CSMEM>>>(
        h1, dwk, dwb, h2);
    // 9) out = xmid + h2 @ w2f + b2f (fp32 out, K=768)
    gemm_k<2, false><<<dim3(2, MCH), 256, GSMEM_TOTAL>>>(
        h2, wp + WP_F2, b2f, xmid, out, 192, 768);
}

// round 14
// speedup vs baseline: 1.0983x; 1.0983x over previous
#include <cuda_runtime.h>
#include <cuda_bf16.h>
#include <math.h>
#include <stdint.h>

#define BATCH   2
#define IMH     256
#define IMW     256
#define C       192
#define HEADS   6
#define HD      32
#define HIDDEN  768
#define HW      (IMH*IMW)
#define M_TOK   (BATCH*HW)          // 131072
#define SCALE_Q 0.17677669529663687f

typedef __nv_bfloat16  bf16;
typedef __nv_bfloat162 bf162;

// ---------------- scratch buffers (device globals; no allocation) -----------
__device__ bf16  g_xn  [M_TOK * C];
__device__ bf16  g_q   [M_TOK * C];
__device__ bf16  g_kv  [M_TOK * (C/2)];
__device__ bf16  g_aw  [M_TOK * C];
__device__ float g_xmid[M_TOK * C];
__device__ bf16  g_h1  [(size_t)M_TOK * HIDDEN];
__device__ bf16  g_h2  [(size_t)M_TOK * HIDDEN];
__device__ bf16  g_wp  [387072];     // packed [N][K] bf16 weights
#define WP_Q    0
#define WP_KV   36864
#define WP_PROJ 55296
#define WP_F1   92160
#define WP_F2   239616

__device__ __forceinline__ uint32_t bf2(float lo, float hi) {
    bf162 h = __floats2bfloat162_rn(lo, hi);
    return *(uint32_t*)&h;
}

// ---------------- weight pre-pack (all 5 matrices, one launch) --------------
__global__ void pack_all(const float* __restrict__ wq,
                         const float* __restrict__ wkv,
                         const float* __restrict__ wproj,
                         const float* __restrict__ w1f,
                         const float* __restrict__ w2f,
                         bf16* __restrict__ out) {
    int idx = blockIdx.x * 256 + threadIdx.x;
    if (idx >= 387072) return;
    const float* W; int K, N, off;
    if      (idx < WP_KV)   { W = wq;    K = 192; N = 192; off = WP_Q;    }
    else if (idx < WP_PROJ) { W = wkv;   K = 192; N = 96;  off = WP_KV;   }
    else if (idx < WP_F1)   { W = wproj; K = 192; N = 192; off = WP_PROJ; }
    else if (idx < WP_F2)   { W = w1f;   K = 192; N = 768; off = WP_F1;   }
    else                    { W = w2f;   K = 768; N = 192; off = WP_F2;   }
    int li = idx - off;
    int n = li / K, k = li - n * K;
    out[idx] = __float2bfloat16(W[(size_t)k * N + n]);
}

// ---------------- LayerNorm: one warp per token, contiguous 6/thread --------
__global__ void ln_kernel(const float* __restrict__ x,
                          const float* __restrict__ g,
                          const float* __restrict__ b,
                          bf16* __restrict__ out) {
    int token = blockIdx.x * blockDim.y + threadIdx.y;
    int lane  = threadIdx.x;
    const float* row = x + (size_t)token * C + lane * 6;
    float v[6];
#pragma unroll
    for (int i = 0; i < 3; i++)
        *(float2*)&v[2*i] = *(const float2*)(row + 2*i);
    float s = 0.f;
#pragma unroll
    for (int i = 0; i < 6; i++) s += v[i];
#pragma unroll
    for (int o = 16; o > 0; o >>= 1) s += __shfl_xor_sync(0xffffffffu, s, o);
    float mean = s * (1.0f / C);
    float s2 = 0.f;
#pragma unroll
    for (int i = 0; i < 6; i++) { float d = v[i] - mean; s2 += d * d; }
#pragma unroll
    for (int o = 16; o > 0; o >>= 1) s2 += __shfl_xor_sync(0xffffffffu, s2, o);
    float rstd = rsqrtf(s2 * (1.0f / C) + 1e-5f);
    float gv[6], bv[6];
#pragma unroll
    for (int i = 0; i < 3; i++) {
        *(float2*)&gv[2*i] = *(const float2*)(g + lane*6 + 2*i);
        *(float2*)&bv[2*i] = *(const float2*)(b + lane*6 + 2*i);
    }
    uint32_t* orow = (uint32_t*)(out + (size_t)token * C + lane * 6);
#pragma unroll
    for (int i = 0; i < 3; i++) {
        float a0 = (v[2*i]   - mean) * rstd * gv[2*i]   + bv[2*i];
        float a1 = (v[2*i+1] - mean) * rstd * gv[2*i+1] + bv[2*i+1];
        orow[i] = bf2(a0, a1);
    }
}

// ---------------- bf16 tensor-core GEMM: cp.async 3-stage, BK=64 ------------
// OUT[M,N] = epi( A[M,K] @ Wp^T + bias ), Wp packed [N][K] bf16.
// BM=128, BN=96, BK=64, 256 threads = 8 warps 4(m)x2(n), warp tile 32x48.
// Row = 128B data + 16B pad (144B): 16*r mod 128 distinct for r in 0..7 =>
// conflict-free ldmatrix without swizzle. One wait+barrier per 64 k.

#define STAGES      3
#define A_STAGE_B   (128*144)                // 18432
#define B_STAGE_B   (96*144)                 // 13824
#define STAGE_B     (A_STAGE_B + B_STAGE_B)  // 32256
#define GSMEM_TOTAL (STAGES * STAGE_B)       // 96768

__device__ __forceinline__ void mma_bf16(float* d, const uint32_t* a,
                                         uint32_t b0, uint32_t b1) {
    asm volatile(
        "mma.sync.aligned.m16n8k16.row.col.f32.bf16.bf16.f32 "
        "{%0,%1,%2,%3},{%4,%5,%6,%7},{%8,%9},{%0,%1,%2,%3};"
        : "+f"(d[0]), "+f"(d[1]), "+f"(d[2]), "+f"(d[3])
        : "r"(a[0]), "r"(a[1]), "r"(a[2]), "r"(a[3]), "r"(b0), "r"(b1));
}
__device__ __forceinline__ void ldsm4(uint32_t& r0, uint32_t& r1,
                                      uint32_t& r2, uint32_t& r3,
                                      uint32_t addr) {
    asm volatile(
        "ldmatrix.sync.aligned.m8n8.x4.shared.b16 {%0,%1,%2,%3}, [%4];"
        : "=r"(r0), "=r"(r1), "=r"(r2), "=r"(r3) : "r"(addr));
}
__device__ __forceinline__ void cp16(uint32_t dst, const void* src) {
    asm volatile("cp.async.cg.shared.global [%0], [%1], 16;"
                 :: "r"(dst), "l"(src));
}
#define CP_COMMIT()  asm volatile("cp.async.commit_group;")
#define CP_WAIT1()   asm volatile("cp.async.wait_group 1;")

__device__ __forceinline__ uint32_t smem_u32(const void* p) {
    uint32_t a;
    asm("{ .reg .u64 t; cvta.to.shared.u64 t, %1; cvt.u32.u64 %0, t; }"
        : "=r"(a) : "l"(p));
    return a;
}

__device__ __forceinline__ void
issue_stage(uint32_t sbase, int stage, const bf16* __restrict__ A,
            const bf16* __restrict__ Wp, int K, int m0, int n0,
            int kt, int tid) {
    uint32_t ab = sbase + stage * STAGE_B;
    uint32_t bb = ab + A_STAGE_B;
    // A: 1024 16B-chunks (128 rows x 8), 4 per thread
#pragma unroll
    for (int r = 0; r < 4; r++) {
        int i = tid + r * 256;
        cp16(ab + (i >> 3) * 144 + (i & 7) * 16,
             A + (size_t)(m0 + (i >> 3)) * K + kt * 64 + (i & 7) * 8);
    }
    // B: 768 chunks (96 rows x 8), 3 per thread
#pragma unroll
    for (int r = 0; r < 3; r++) {
        int i = tid + r * 256;
        cp16(bb + (i >> 3) * 144 + (i & 7) * 16,
             Wp + (size_t)(n0 + (i >> 3)) * K + kt * 64 + (i & 7) * 8);
    }
}

template<int EPI, bool OUT_BF16>
__device__ __forceinline__ void
gemm_body(char* sm, const bf16* __restrict__ A, const bf16* __restrict__ Wp,
          const float* __restrict__ bias, const float* __restrict__ res,
          void* __restrict__ outv, int N, int K, int n0, int m0) {
    const int tid  = threadIdx.x;
    const int wid  = tid >> 5, lane = tid & 31;
    const int wm   = wid >> 1, wn = wid & 1;
    const int gid  = lane >> 2, tig = lane & 3;

    uint32_t sbase = smem_u32(sm);

    uint32_t a_off[2], b_off[3];
#pragma unroll
    for (int mt = 0; mt < 2; mt++)
        a_off[mt] = (wm*32 + mt*16 + (lane & 15)) * 144 + (lane >> 4) * 16;
#pragma unroll
    for (int p = 0; p < 3; p++)
        b_off[p] = A_STAGE_B +
            (wn*48 + p*16 + ((lane >> 4) & 1)*8 + (lane & 7)) * 144 +
            ((lane >> 3) & 1) * 16;

    float acc[2][6][4];
#pragma unroll
    for (int mt = 0; mt < 2; mt++)
#pragma unroll
        for (int nt = 0; nt < 6; nt++)
#pragma unroll
            for (int r = 0; r < 4; r++) acc[mt][nt][r] = 0.f;

    const int nk = K / 64;

    // prologue: 2 stages in flight
#pragma unroll
    for (int p = 0; p < STAGES - 1; p++) {
        if (p < nk) issue_stage(sbase, p, A, Wp, K, m0, n0, p, tid);
        CP_COMMIT();
    }

    int stage = 0;
    for (int kt = 0; kt < nk; kt++) {
        CP_WAIT1();
        __syncthreads();

        uint32_t sb = sbase + stage * STAGE_B;
#pragma unroll
        for (int s = 0; s < 4; s++) {
            uint32_t af[2][4];
#pragma unroll
            for (int mt = 0; mt < 2; mt++)
                ldsm4(af[mt][0], af[mt][1], af[mt][2], af[mt][3],
                      sb + a_off[mt] + s*32);
            uint32_t bfr[3][4];
#pragma unroll
            for (int p = 0; p < 3; p++)
                ldsm4(bfr[p][0], bfr[p][1], bfr[p][2], bfr[p][3],
                      sb + b_off[p] + s*32);
#pragma unroll
            for (int nt = 0; nt < 6; nt++) {
                uint32_t b0 = bfr[nt >> 1][(nt & 1)*2];
                uint32_t b1 = bfr[nt >> 1][(nt & 1)*2 + 1];
#pragma unroll
                for (int mt = 0; mt < 2; mt++)
                    mma_bf16(acc[mt][nt], af[mt], b0, b1);
            }
        }

        int nx = kt + STAGES - 1;
        if (nx < nk) {
            int ns = stage + STAGES - 1;
            if (ns >= STAGES) ns -= STAGES;
            issue_stage(sbase, ns, A, Wp, K, m0, n0, nx, tid);
        }
        CP_COMMIT();
        if (++stage == STAGES) stage = 0;
    }

    // epilogue
#pragma unroll
    for (int nt = 0; nt < 6; nt++) {
        int cb = n0 + wn*48 + nt*8 + 2*tig;
        float b0 = bias[cb], b1 = bias[cb + 1];
#pragma unroll
        for (int mt = 0; mt < 2; mt++) {
            int r0 = m0 + wm*32 + mt*16 + gid;
#pragma unroll
            for (int hh = 0; hh < 2; hh++) {
                int r = r0 + hh*8;
                float v0 = acc[mt][nt][hh*2 + 0] + b0;
                float v1 = acc[mt][nt][hh*2 + 1] + b1;
                if (EPI == 1) { v0 = v0 * normcdff(v0); v1 = v1 * normcdff(v1); }
                if (EPI == 2) {
                    const float* rr = res + (size_t)r * N + cb;
                    v0 += rr[0]; v1 += rr[1];
                }
                if (OUT_BF16)
                    *(uint32_t*)((bf16*)outv + (size_t)r * N + cb) = bf2(v0, v1);
                else
                    *(float2*)((float*)outv + (size_t)r * N + cb) =
                        make_float2(v0, v1);
            }
        }
    }
}

template<int EPI, bool OUT_BF16>
__global__ void __launch_bounds__(256, 2)
gemm_k(const bf16* __restrict__ A, const bf16* __restrict__ Wp,
       const float* __restrict__ bias, const float* __restrict__ res,
       void* __restrict__ out, int N, int K) {
    extern __shared__ char sm[];
    gemm_body<EPI, OUT_BF16>(sm, A, Wp, bias, res, out, N, K,
                             blockIdx.x * 96, blockIdx.y * 128);
}

__global__ void __launch_bounds__(256, 2)
gemm_qkv(const bf16* __restrict__ A,
         const bf16* __restrict__ Wq,  const float* __restrict__ bq,
         bf16* __restrict__ qout,
         const bf16* __restrict__ Wkv, const float* __restrict__ bkv,
         bf16* __restrict__ kvout) {
    extern __shared__ char sm[];
    if (blockIdx.x < 2)
        gemm_body<0, true>(sm, A, Wq, bq, nullptr, qout, 192, 192,
                           blockIdx.x * 96, blockIdx.y * 128);
    else
        gemm_body<0, true>(sm, A, Wkv, bkv, nullptr, kvout, 96, 192,
                           0, blockIdx.y * 128);
}

// ---------------- fused window attention (vectorized kv gather) -------------
__global__ void __launch_bounds__(384)
attn_kernel(const bf16* __restrict__ q, const bf16* __restrict__ kv,
            const float* __restrict__ table, bf16* __restrict__ aw) {
    __shared__ float ks[16*192];
    __shared__ float vs[16*192];
    __shared__ float tb[49*HEADS];

    int w  = blockIdx.x;
    int bb = w >> 10;
    int wi = w & 1023;
    int wy = wi >> 5, wx = wi & 31;
    size_t base = (size_t)bb * HW + (size_t)(wy*8) * IMW + wx*8;
    int tid = threadIdx.x;

    for (int e = tid; e < 49*HEADS; e += 384) tb[e] = table[e];

    // vectorized gather + permute: 768 uint4 (8 bf16 each), 2 per thread
#pragma unroll
    for (int rep = 0; rep < 2; rep++) {
        int e = tid + rep * 384;
        int s = e / 12, j = e - s * 12;
        int r = s >> 3, c = s & 7;
        const uint4* src4 = (const uint4*)(kv +
            (base + (size_t)r * IMW + c) * (C/2));
        uint4 t = src4[j];
        uint32_t u[4] = {t.x, t.y, t.z, t.w};
        float f8[8];
#pragma unroll
        for (int i = 0; i < 4; i++) {
            float2 f2 = __bfloat1622float2(*(bf162*)&u[i]);
            f8[2*i] = f2.x; f8[2*i+1] = f2.y;
        }
        int p  = (r >> 1) * 4 + (c >> 1);
        bool isk = (j < 6);
        int cc0 = (isk ? j : j - 6) * 8;
        float* dst = (isk ? ks : vs) + p*192 + (r & 1)*96 + (c & 1)*48 + cc0;
        *(float4*)dst       = make_float4(f8[0], f8[1], f8[2], f8[3]);
        *(float4*)(dst + 4) = make_float4(f8[4], f8[5], f8[6], f8[7]);
    }
    __syncthreads();

    int h  = tid / 64;
    int qt = tid & 63;
    int r  = qt >> 3, c = qt & 7;
    int ph = r >> 1, pw = c >> 1;

    size_t tok = base + (size_t)r * IMW + c;
    const uint4* q4 = (const uint4*)(q + tok * C + h*HD);
    float qr[HD];
#pragma unroll
    for (int i = 0; i < 4; i++) {
        uint4 t = q4[i];
        uint32_t u[4] = {t.x, t.y, t.z, t.w};
#pragma unroll
        for (int j = 0; j < 4; j++) {
            float2 f2 = __bfloat1622float2(*(bf162*)&u[j]);
            qr[i*8 + 2*j]     = f2.x * SCALE_Q;
            qr[i*8 + 2*j + 1] = f2.y * SCALE_Q;
        }
    }

    float s[16], m = -1e30f;
#pragma unroll
    for (int kt = 0; kt < 16; kt++) {
        int kh = kt >> 2, kw = kt & 3;
        float acc = tb[((ph - kh + 3) * 7 + (pw - kw + 3)) * HEADS + h];
        const float* kr = &ks[kt*192 + h*HD];
#pragma unroll
        for (int d = 0; d < HD; d++) acc += qr[d] * kr[d];
        s[kt] = acc;
        m = fmaxf(m, acc);
    }
    float sum = 0.f;
#pragma unroll
    for (int kt = 0; kt < 16; kt++) { s[kt] = __expf(s[kt] - m); sum += s[kt]; }
    float inv = 1.0f / sum;

    float ov[HD];
#pragma unroll
    for (int d = 0; d < HD; d++) {
        float o = 0.f;
#pragma unroll
        for (int kt = 0; kt < 16; kt++) o += s[kt] * vs[kt*192 + h*HD + d];
        ov[d] = o * inv;
    }
    uint4* ow = (uint4*)(aw + tok * C + h*HD);
#pragma unroll
    for (int i = 0; i < 4; i++) {
        uint4 t;
        t.x = bf2(ov[i*8+0], ov[i*8+1]);
        t.y = bf2(ov[i*8+2], ov[i*8+3]);
        t.z = bf2(ov[i*8+4], ov[i*8+5]);
        t.w = bf2(ov[i*8+6], ov[i*8+7]);
        ow[i] = t;
    }
}

// ---------------- depthwise 5x5 conv + gelu + add (bf16 I/O) ----------------
__global__ void __launch_bounds__(256)
dwconv_kernel(const bf16* __restrict__ h1, const float* __restrict__ dwk,
              const float* __restrict__ dwb, bf16* __restrict__ out) {
    constexpr int TS = 16, CCH = 32, TT = TS + 4;
    extern __shared__ float smem[];
    float* tile = smem;
    float* wk   = tile + TT*TT*CCH;
    float* bk   = wk + CCH*25;

    int bz = blockIdx.z;
    int bb = bz / (HIDDEN / CCH);
    int c0 = (bz % (HIDDEN / CCH)) * CCH;
    int x0 = blockIdx.x * TS, y0 = blockIdx.y * TS;
    int tid = threadIdx.x;

    for (int e = tid; e < CCH*25; e += 256) {
        int cc = e / 25, t = e - cc*25;
        wk[cc*25 + t] = dwk[(c0 + cc) * 25 + t];
    }
    if (tid < CCH) bk[tid] = dwb[c0 + tid];

    for (int e = tid; e < TT*TT*(CCH/8); e += 256) {
        int pos = e / (CCH/8);
        int qv  = e - pos*(CCH/8);
        int py = pos / TT, px = pos - py*TT;
        int gy = y0 + py - 2, gx = x0 + px - 2;
        float f[8] = {0,0,0,0,0,0,0,0};
        if (gy >= 0 && gy < IMH && gx >= 0 && gx < IMW) {
            uint4 t = *(const uint4*)(h1 +
                ((size_t)bb*HW + (size_t)gy*IMW + gx)*HIDDEN + c0 + qv*8);
            uint32_t u[4] = {t.x, t.y, t.z, t.w};
#pragma unroll
            for (int j = 0; j < 4; j++) {
                float2 f2 = __bfloat1622float2(*(bf162*)&u[j]);
                f[2*j] = f2.x; f[2*j+1] = f2.y;
            }
        }
        float* dst = &tile[(py*TT + px)*CCH + qv*8];
#pragma unroll
        for (int j = 0; j < 8; j++) dst[j] = f[j];
    }
    __syncthreads();

    int cc = tid & (CCH-1);
    int st = tid >> 5;
    const float* wr = &wk[cc*25];
    float bia = bk[cc];

    for (int it = 0; it < 8; it++) {
        int task = it*8 + st;
        int x  = task & 15;
        int ys = task >> 4;
        float acc[4] = {0.f, 0.f, 0.f, 0.f};
#pragma unroll
        for (int rr = 0; rr < 8; rr++) {
            int py = ys*4 + rr;
            float v[5];
#pragma unroll
            for (int dx = 0; dx < 5; dx++)
                v[dx] = tile[(py*TT + x + dx)*CCH + cc];
#pragma unroll
            for (int j = 0; j < 4; j++) {
                int ky = rr - j;
                if (ky >= 0 && ky < 5) {
#pragma unroll
                    for (int dx = 0; dx < 5; dx++)
                        acc[j] += v[dx] * wr[ky*5 + dx];
                }
            }
        }
#pragma unroll
        for (int j = 0; j < 4; j++) {
            int y = ys*4 + j;
            float rj = tile[((y+2)*TT + (x+2))*CCH + cc];
            float gv = acc[j] + bia;
            gv = gv * normcdff(gv);
            size_t o = ((size_t)bb*HW + (size_t)(y0+y)*IMW + (x0+x))*HIDDEN
                     + c0 + cc;
            out[o] = __float2bfloat16(rj + gv);
        }
    }
}

// ---------------- launch ----------------------------------------------------
extern "C" void kernel_launch(void* const* d_in, const int* in_sizes, int n_in,
                              void* d_out, int out_size) {
    const float* x     = (const float*)d_in[0];
    const float* g1    = (const float*)d_in[1];
    const float* be1   = (const float*)d_in[2];
    const float* wq    = (const float*)d_in[3];
    const float* bq    = (const float*)d_in[4];
    const float* wkv   = (const float*)d_in[5];
    const float* bkv   = (const float*)d_in[6];
    const float* table = (const float*)d_in[7];
    const float* wproj = (const float*)d_in[8];
    const float* bproj = (const float*)d_in[9];
    const float* g2    = (const float*)d_in[10];
    const float* be2   = (const float*)d_in[11];
    const float* w1f   = (const float*)d_in[12];
    const float* b1f   = (const float*)d_in[13];
    const float* dwk   = (const float*)d_in[14];
    const float* dwb   = (const float*)d_in[15];
    const float* w2f   = (const float*)d_in[16];
    const float* b2f   = (const float*)d_in[17];
    float* out = (float*)d_out;

    void *pxn, *pq, *pkv, *paw, *pxmid, *ph1, *ph2, *pwp;
    cudaGetSymbolAddress(&pxn,   g_xn);
    cudaGetSymbolAddress(&pq,    g_q);
    cudaGetSymbolAddress(&pkv,   g_kv);
    cudaGetSymbolAddress(&paw,   g_aw);
    cudaGetSymbolAddress(&pxmid, g_xmid);
    cudaGetSymbolAddress(&ph1,   g_h1);
    cudaGetSymbolAddress(&ph2,   g_h2);
    cudaGetSymbolAddress(&pwp,   g_wp);
    bf16*  xn   = (bf16*)pxn;
    bf16*  qb   = (bf16*)pq;
    bf16*  kvb  = (bf16*)pkv;
    bf16*  awb  = (bf16*)paw;
    float* xmid = (float*)pxmid;
    bf16*  h1   = (bf16*)ph1;
    bf16*  h2   = (bf16*)ph2;
    bf16*  wp   = (bf16*)pwp;

    const int CSMEM = (20*20*32 + 32*25 + 32) * 4;
    cudaFuncSetAttribute(dwconv_kernel,
        cudaFuncAttributeMaxDynamicSharedMemorySize, CSMEM);
    cudaFuncSetAttribute(gemm_k<2, false>,
        cudaFuncAttributeMaxDynamicSharedMemorySize, GSMEM_TOTAL);
    cudaFuncSetAttribute(gemm_k<1, true>,
        cudaFuncAttributeMaxDynamicSharedMemorySize, GSMEM_TOTAL);
    cudaFuncSetAttribute(gemm_qkv,
        cudaFuncAttributeMaxDynamicSharedMemorySize, GSMEM_TOTAL);

    dim3 lnb(32, 8);
    const int MB = M_TOK / 128;   // 1024 m-blocks

    // 0) pack all weights to bf16 [N][K]
    pack_all<<<(387072 + 255)/256, 256>>>(wq, wkv, wproj, w1f, w2f, wp);

    // 1) LN1 -> xn (bf16)
    ln_kernel<<<M_TOK/8, lnb>>>(x, g1, be1, xn);
    // 2+3) fused q & kv projections
    gemm_qkv<<<dim3(3, MB), 256, GSMEM_TOTAL>>>(xn, wp + WP_Q, bq, qb,
                                                wp + WP_KV, bkv, kvb);
    // 4) window attention -> aw (bf16)
    attn_kernel<<<2048, 384>>>(qb, kvb, table, awb);
    // 5) xmid = x + aw @ wproj + bproj (fp32 out)
    gemm_k<2, false><<<dim3(2, MB), 256, GSMEM_TOTAL>>>(
        awb, wp + WP_PROJ, bproj, x, xmid, 192, 192);
    // 6) LN2 -> xn
    ln_kernel<<<M_TOK/8, lnb>>>(xmid, g2, be2, xn);
    // 7) h1 = gelu(xn @ w1f + b1f)
    gemm_k<1, true><<<dim3(8, MB), 256, GSMEM_TOTAL>>>(
        xn, wp + WP_F1, b1f, nullptr, h1, 768, 192);
    // 8) h2 = h1 + gelu(dwconv(h1) + dwb)
    dwconv_kernel<<<dim3(IMW/16, IMH/16, BATCH*(HIDDEN/32)), 256, CSMEM>>>(
        h1, dwk, dwb, h2);
    // 9) out = xmid + h2 @ w2f + b2f (fp32 out, K=768)
    gemm_k<2, false><<<dim3(2, MB), 256, GSMEM_TOTAL>>>(
        h2, wp + WP_F2, b2f, xmid, out, 192, 768);
}